// round 8
// baseline (speedup 1.0000x reference)
#include <cuda_runtime.h>
#include <cuda_fp16.h>
#include <math.h>

// ---------------- static scratch (no cudaMalloc allowed) ----------------
#define S3 144                     // padded emission row: j=0 blank, j=1..L labels
#define E_CAP (1600 * 48 * S3)     // T*B*S3 for this problem's shapes
__device__ __half g_E[E_CAP];      // E[t][b][j] = lp[t][b][label_j]  (fp16)
__device__ double g_tot[4096];
__device__ int    g_cnt = 0;

// ---------------- volatile 128-bit shared access helpers ----------------
__device__ __forceinline__ uint4 lds128v(const void* p) {
  uint4 r;
  unsigned sa = (unsigned)__cvta_generic_to_shared(p);
  asm volatile("ld.volatile.shared.v4.u32 {%0,%1,%2,%3}, [%4];"
               : "=r"(r.x), "=r"(r.y), "=r"(r.z), "=r"(r.w) : "r"(sa));
  return r;
}
__device__ __forceinline__ void sts128v(void* p, uint4 v) {
  unsigned sa = (unsigned)__cvta_generic_to_shared(p);
  asm volatile("st.volatile.shared.v4.u32 [%0], {%1,%2,%3,%4};"
               :: "r"(sa), "r"(v.x), "r"(v.y), "r"(v.z), "r"(v.w));
}

// ---------------- kernel 1: emission gather (full chip) ----------------
// One block per timestep streams the 192KB t-slab; writes coalesced fp16.
__global__ void ctc_gather(const float* __restrict__ lp,
                           const int* __restrict__ tg,
                           int B, int V, int L) {
  const int t = blockIdx.x;
  const float* row = lp + (size_t)t * B * V;
  __half* erow = g_E + (size_t)t * B * S3;
  const int n = B * S3;
  for (int i = threadIdx.x; i < n; i += blockDim.x) {
    const int b = i / S3, j = i - b * S3;
    int lab = 0;
    if (j >= 1 && j <= L) lab = tg[b * L + j - 1];
    erow[i] = __float2half_rn(row[b * V + lab]);
  }
}

// ---------------- kernel 2: decoupled-warp linear-domain scan ----------------
// One CTA per utterance. Thread s owns state s; alphas in registers; intra-warp
// neighbors via shfl; cross-warp boundary via a 128-deep smem ring per boundary.
// Per-warp exact power-of-two scaling every 8 steps.
__global__ void ctc_scan(const int* __restrict__ tg,
                         const int* __restrict__ ilen,
                         float* __restrict__ out,
                         int B, int L, int T) {
  const int b = blockIdx.x;
  const int S = 2 * L + 1;
  const int s = threadIdx.x;
  const int lane = s & 31, wid = s >> 5;
  const int NW = (int)(blockDim.x >> 5);

  __shared__ uint4 ring[8][128];          // boundary w: producer warp w -> consumer w+1
  __shared__ volatile int prog[16];       // consumer window progress (back-pressure)
  __shared__ float fin[2];
  __shared__ int   finE[2];

  for (int i = s; i < 8 * 128; i += blockDim.x) ring[i >> 7][i & 127].w = 0xFFFFFFFFu;
  if (s < 16) prog[s] = 0;

  const bool valid = (s < S);
  const float validf = valid ? 1.0f : 0.0f;
  float skipw = 0.0f;
  int j_e = 0;  // column in E row (0 = blank)
  if (valid && (s & 1)) {
    const int l = s >> 1;
    const int lab = tg[b * L + l];
    j_e = 1 + l;
    if (s >= 2 && lab != tg[b * L + l - 1]) skipw = 1.0f;
  }
  const __half* eptr = g_E + (size_t)b * S3 + j_e;
  const size_t estride = (size_t)B * S3;   // elements per timestep
  const int len = ilen[b];

  float a = 0.0f;
  int Ecum = 0, EpLast = 0;
  uint4 eCur; eCur.w = 0xFFFFFFFFu;        // speculative ring-entry register

  const int G = 8;
  __half lpv[G];
#pragma unroll
  for (int j = 0; j < G; j++) {
    const int t = 1 + j;
    lpv[j] = (t < len) ? __ldg(eptr + (size_t)t * estride) : __half(0);
  }
  __syncthreads();                         // ring init visible; warps decouple after this
  if (s < 2) a = __expf(__half2float(__ldg(eptr)));  // t = 0 init

  for (int tb = 1; tb < len; tb += G) {
    // ---- window top: per-warp rescale (warp max -> ~2^30), exact power of 2.
    const unsigned mu = __reduce_max_sync(0xffffffffu, __float_as_uint(a));
    if (mu != 0u) {
      int k = 30 - ((int)((mu >> 23) & 255u) - 127);
      k = k > 127 ? 127 : (k < -126 ? -126 : k);
      a *= __int_as_float((127 + k) << 23);
      Ecum -= k;
    } else {
      Ecum = __shfl_sync(0xffffffffu, EpLast, 0);  // empty warp adopts producer scale
    }
    // progress publish (consumer role) + back-pressure (producer role)
    if (wid > 0 && lane == 0) prog[wid] = tb;
    if (wid < NW - 1 && lane == 31)
      while (tb - prog[wid + 1] > 96) __nanosleep(64);

    // prefetch next window's emissions; exponentiate this window's (off chain)
    __half lpn[G];
#pragma unroll
    for (int j = 0; j < G; j++) {
      const int t = tb + G + j;
      lpn[j] = (t < len) ? __ldg(eptr + (size_t)t * estride) : __half(0);
    }
    float pv[G];
#pragma unroll
    for (int j = 0; j < G; j++) pv[j] = __expf(__half2float(lpv[j])) * validf;

#pragma unroll
    for (int j = 0; j < G; j++) {
      const int tau = tb + j;
      if (tau < len) {                       // block-uniform guard
        const float a1 = __shfl_up_sync(0xffffffffu, a, 1);
        const float a2 = __shfl_up_sync(0xffffffffu, a, 2);
        // producer: publish alpha(tau-1) at the warp's top state (a is pre-update)
        if (wid < NW - 1 && lane == 31) {
          uint4 e4;
          e4.x = __float_as_uint(a); e4.y = 0u;
          e4.z = (unsigned)Ecum;     e4.w = (unsigned)(tau - 1);
          sts128v(&ring[wid][(tau - 1) & 127], e4);
        }
        // consumer lanes 0,1: boundary value alpha(tau-1, s_prev_top), rescaled
        float bs = 0.0f;
        if (wid > 0 && lane < 2) {
          const unsigned want = (unsigned)(tau - 1);
          if (eCur.w != want) {
            do {
              eCur = lds128v(&ring[wid - 1][(tau - 1) & 127]);
              if (eCur.w == want) break;
              __nanosleep(32);
            } while (true);
          }
          const float b31 = __uint_as_float(eCur.x);
          const int Ep = (int)eCur.z;
          EpLast = Ep;
          int dE = Ep - Ecum;
          dE = dE < -252 ? -252 : (dE > 252 ? 252 : dE);
          const int d1 = dE >> 1, d2 = dE - d1;
          bs = b31 * __int_as_float((127 + d1) << 23)
                   * __int_as_float((127 + d2) << 23);
          // speculative prefetch of next step's entry (latency hidden by FMA chain)
          eCur = lds128v(&ring[wid - 1][tau & 127]);
        }
        const float a1p = (lane == 0) ? bs : a1;  // lane0: s-1 crosses boundary
        const float a2p = (lane == 1) ? bs : a2;  // lane1: s-2 crosses boundary
        a = (a + a1p + skipw * a2p) * pv[j];      // lane0 is even state: skipw=0
      }
    }
#pragma unroll
    for (int j = 0; j < G; j++) lpv[j] = lpn[j];
  }

  // ---- readout: final-state alphas + their warps' exponents, double log space
  if (s == S - 1) { fin[0] = a; finE[0] = Ecum; }
  if (s == S - 2) { fin[1] = a; finE[1] = Ecum; }
  __syncthreads();
  if (s == 0) {
    const double l1 = (fin[0] > 0.0f) ? log2((double)fin[0]) + (double)finE[0] : -4e9;
    const double l2 = (fin[1] > 0.0f) ? log2((double)fin[1]) + (double)finE[1] : -4e9;
    const double m = fmax(l1, l2);
    g_tot[b] = (m + log2(exp2(l1 - m) + exp2(l2 - m))) * 0.6931471805599453;
    __threadfence();
    const int c = atomicAdd(&g_cnt, 1);
    if (c == B - 1) {                 // last block: deterministic fixed-order sum
      __threadfence();
      double acc = 0.0;
      for (int i = 0; i < B; i++) acc += g_tot[i];
      out[0] = (float)(-acc);
      atomicExch(&g_cnt, 0);          // reset for next graph replay
    }
  }
}

extern "C" void kernel_launch(void* const* d_in, const int* in_sizes, int n_in,
                              void* d_out, int out_size) {
  const float* lp      = (const float*)d_in[0];  // [T, B, V] log-softmax
  const int*   targets = (const int*)d_in[1];    // [B*L]
  const int*   ilen    = (const int*)d_in[2];    // [B]
  (void)n_in; (void)out_size;

  const int B = in_sizes[2];
  const int L = in_sizes[1] / B;
  const int V = 1000;                            // vocab (blank = 0)
  const int T = in_sizes[0] / (B * V);
  const int S = 2 * L + 1;
  const int NT = ((S + 31) / 32) * 32;           // 288 threads for S=257

  ctc_gather<<<T, 512>>>(lp, targets, B, V, L);
  ctc_scan<<<B, NT>>>(targets, ilen, (float*)d_out, B, L, T);
}